// round 9
// baseline (speedup 1.0000x reference)
#include <cuda_runtime.h>
#include <math.h>
#include <float.h>

#define B_   16
#define C_   64
#define N_   2048
#define K_   20
#define OUT_ 128
#define G_   (B_*N_)          // 32768 columns
#define TN   8                // columns per block
#define NBLK (G_/TN)          // 4096
#define THR  256
#define FSTR 1284             // padded per-column stride (floats)
#define EPS_ 1e-5f

// ---- device scratch (no allocations allowed) ----
__device__ float g_xT[G_*C_];             // 8 MB: x transposed to (B*N, C)
__device__ float g_P[G_*64];              // 8 MB: P[p][o] = W4a . xT[p]
__device__ float g_Q[G_*64];              // 8 MB: Q[g][o] = (W4b-W4a) . xT[g]
__device__ float g_part[NBLK*OUT_*2];     // 4 MB: per-block (sum, sumsq) per channel
__device__ float g_scale[OUT_];
__device__ float g_shift[OUT_];

// ============================================================
// Kernel 0: transpose x (B,C,N) -> xT (B*N, C), smem-tiled
// ============================================================
__global__ void transpose_k(const float* __restrict__ x) {
    __shared__ float t[32][33];
    int b  = blockIdx.z;
    int n0 = blockIdx.x * 32, c0 = blockIdx.y * 32;
    int tx = threadIdx.x, ty = threadIdx.y;
    #pragma unroll
    for (int i = ty; i < 32; i += 8)
        t[i][tx] = x[((size_t)b*C_ + c0 + i)*N_ + n0 + tx];
    __syncthreads();
    #pragma unroll
    for (int i = ty; i < 32; i += 8)
        g_xT[((size_t)b*N_ + n0 + i)*C_ + c0 + tx] = t[tx][i];
}

// ============================================================
// Kernel 0b: P/Q precompute.  P[p][o] = sum_c W4a[o][c] xT[p][c],
//            Q[p][o] = sum_c (W4b-W4a)[o][c] xT[p][c].
// ============================================================
__global__ __launch_bounds__(256)
void pq_k(const float* __restrict__ W4) {
    __shared__ float X[64*68];
    __shared__ float WW[128*68];
    const int tid = threadIdx.x;
    const int p0  = blockIdx.x * 64;

    // WW rows 0..63 = W4a, rows 64..127 = W4b - W4a
    for (int j = tid; j < 64*16; j += 256) {
        int o = j >> 4, q = j & 15;
        float4 a = ((const float4*)W4)[o*32 + q];
        float4 b = ((const float4*)W4)[o*32 + 16 + q];
        float* d = &WW[o*68 + q*4];
        d[0]=a.x; d[1]=a.y; d[2]=a.z; d[3]=a.w;
        float* e = &WW[(64+o)*68 + q*4];
        e[0]=b.x-a.x; e[1]=b.y-a.y; e[2]=b.z-a.z; e[3]=b.w-a.w;
    }
    for (int j = tid; j < 64*16; j += 256) {
        int r = j >> 4, q = j & 15;
        float4 v = ((const float4*)g_xT)[(size_t)(p0 + r)*16 + q];
        float* d = &X[r*68 + q*4];
        d[0]=v.x; d[1]=v.y; d[2]=v.z; d[3]=v.w;
    }
    __syncthreads();

    const int o  = tid & 63;
    const int ps = tid >> 6;                 // 0..3 -> 16 p-rows each
    const float4* wa = (const float4*)(WW + o*68);
    const float4* wb = (const float4*)(WW + (64+o)*68);
    for (int pl = 0; pl < 16; pl++) {
        int p = ps*16 + pl;
        const float4* xv = (const float4*)(X + p*68);
        float aA0=0.f, aA1=0.f, aB0=0.f, aB1=0.f;
        #pragma unroll
        for (int q = 0; q < 16; q++) {
            float4 xq = xv[q], u = wa[q], v = wb[q];
            aA0 += xq.x*u.x + xq.y*u.y;  aA1 += xq.z*u.z + xq.w*u.w;
            aB0 += xq.x*v.x + xq.y*v.y;  aB1 += xq.z*v.z + xq.w*v.w;
        }
        g_P[(size_t)(p0 + p)*64 + o] = aA0 + aA1;
        g_Q[(size_t)(p0 + p)*64 + o] = aB0 + aB1;
    }
}

// ============================================================
// Kernel 1: fused gather + feats + out2 + out4-combine + partial stats
//   Phase 3 (out2) uses a col-pair map so each W2 load serves 2 columns;
//   P values staged cooperatively into smem (coalesced) for out4.
// ============================================================
__global__ __launch_bounds__(THR, 2)
void main_k(const int*   __restrict__ sidx,
            const float* __restrict__ adjw,
            const float* __restrict__ W2,
            const float* __restrict__ b2,
            float*       __restrict__ out)
{
    extern __shared__ float sm[];
    float* S  = sm;                      // TN*FSTR: S[col][i*64+f]; later Ps[col][i*64+o]
    float* F  = S + TN*FSTR;             // TN*FSTR: feats[col][f*20+k]
    float* AW = F + TN*FSTR;             // TN*400: A[col][i*20+k]; later o2 scratch [col*64+o]
    int*   SX = (int*)(AW + TN*400);     // TN*20 spiral indices

    const int tid = threadIdx.x;
    const int g0  = blockIdx.x * TN;

    // ---- stage spiral indices ----
    if (tid < TN*K_) SX[tid] = sidx[g0*K_ + tid];      // SX[col*20+i]

    // ---- gather spiral rows into S (float4, coalesced over xT rows) ----
    for (int j = tid; j < TN*K_*16; j += THR) {
        int col = j / (K_*16);
        int r   = j % (K_*16);
        int i   = r >> 4, q = r & 15;
        int p   = sidx[(g0 + col)*K_ + i];
        float4 v = ((const float4*)g_xT)[(size_t)p*16 + q];
        float* d = &S[col*FSTR + i*64 + q*4];
        d[0]=v.x; d[1]=v.y; d[2]=v.z; d[3]=v.w;
    }
    // ---- adjweight tile ----
    for (int j = tid; j < TN*100; j += THR) {
        int col = j/100, q = j%100;
        float4 v = ((const float4*)adjw)[(size_t)(g0+col)*100 + q];
        float* d = &AW[col*400 + q*4];
        d[0]=v.x; d[1]=v.y; d[2]=v.z; d[3]=v.w;
    }
    __syncthreads();

    // ---- feats[col][f*20+k] = sum_i S[col][i][f] * A[col][i][k] ----
    #pragma unroll
    for (int pass = 0; pass < 2; pass++) {
        int id   = tid + pass*THR;
        int fcol = id >> 6, f = id & 63;
        float acc[20];
        #pragma unroll
        for (int k = 0; k < 20; k++) acc[k] = 0.f;
        const float* Sc = S  + fcol*FSTR + f;
        const float* Ac = AW + fcol*400;
        #pragma unroll
        for (int i = 0; i < 20; i++) {
            float sv = Sc[i*64];
            #pragma unroll
            for (int k = 0; k < 20; k++) acc[k] += sv * Ac[i*20 + k];
        }
        float* Fd = F + fcol*FSTR + f*20;
        #pragma unroll
        for (int k = 0; k < 20; k++) Fd[k] = acc[k];
    }
    __syncthreads();   // S and AW free after this point (F live)

    // ---- phase 3a: stage P rows into S (coalesced; Ps[col][i*64+o]) ----
    for (int j = tid; j < TN*K_*16; j += THR) {
        int col = j / (K_*16);
        int r   = j % (K_*16);
        int i   = r >> 4, q = r & 15;
        int p   = SX[col*K_ + i];
        float4 v = ((const float4*)g_P)[(size_t)p*16 + q];
        float* d = &S[col*FSTR + i*64 + q*4];
        d[0]=v.x; d[1]=v.y; d[2]=v.z; d[3]=v.w;
    }

    // ---- phase 3b: out2 with col-pair map: o = tid>>2 (0..63), cols {2cp,2cp+1}
    {
        const int o  = tid >> 2;
        const int cp = tid & 3;
        const int cA = cp*2, cB = cp*2 + 1;
        const float4* w  = (const float4*)(W2 + (size_t)o*1280);
        const float4* fA = (const float4*)(F + cA*FSTR);
        const float4* fB = (const float4*)(F + cB*FSTR);
        float aAx=0.f,aAy=0.f,aAz=0.f,aAw=0.f;
        float aBx=0.f,aBy=0.f,aBz=0.f,aBw=0.f;
        #pragma unroll 8
        for (int q = 0; q < 320; q++) {
            float4 u  = w[q];
            float4 pa = fA[q], pb = fB[q];
            aAx += pa.x*u.x; aAy += pa.y*u.y; aAz += pa.z*u.z; aAw += pa.w*u.w;
            aBx += pb.x*u.x; aBy += pb.y*u.y; aBz += pb.z*u.z; aBw += pb.w*u.w;
        }
        float bb = b2[o];
        AW[cA*64 + o] = aAx + aAy + aAz + aAw + bb;
        AW[cB*64 + o] = aBx + aBy + aBz + aBw + bb;
    }
    __syncthreads();

    // ---- phase 4: out4 from staged P + Q, combine, write, stats ----
    const int o0  = tid >> 3;        // 0..31
    const int o1  = o0 + 32;         // 32..63
    const int col = tid & 7;
    const int g   = g0 + col;

    float v20 = AW[col*64 + o0];
    float v21 = AW[col*64 + o1];

    float m0 = -FLT_MAX, m1 = -FLT_MAX;
    {
        const float* Pc = S + col*FSTR;
        #pragma unroll
        for (int i = 0; i < K_; i++) {
            m0 = fmaxf(m0, Pc[i*64 + o0]);
            m1 = fmaxf(m1, Pc[i*64 + o1]);
        }
    }
    float v40 = m0 + g_Q[(size_t)g*64 + o0];
    float v41 = m1 + g_Q[(size_t)g*64 + o1];

    // ---- write pre-BN outputs ----
    {
        int b = g >> 11, n = g & 2047;
        size_t base = ((size_t)b*OUT_)*N_ + n;
        out[base + (size_t)o0*N_]        = v20;
        out[base + (size_t)o1*N_]        = v21;
        out[base + (size_t)(64+o0)*N_]   = v40;
        out[base + (size_t)(64+o1)*N_]   = v41;
    }

    // ---- deterministic per-block stats: butterfly over the 3 col bits ----
    float s20=v20, q20=v20*v20, s21=v21, q21=v21*v21;
    float s40=v40, q40=v40*v40, s41=v41, q41=v41*v41;
    #pragma unroll
    for (int off = 1; off < 8; off <<= 1) {
        s20 += __shfl_xor_sync(0xffffffffu, s20, off);
        q20 += __shfl_xor_sync(0xffffffffu, q20, off);
        s21 += __shfl_xor_sync(0xffffffffu, s21, off);
        q21 += __shfl_xor_sync(0xffffffffu, q21, off);
        s40 += __shfl_xor_sync(0xffffffffu, s40, off);
        q40 += __shfl_xor_sync(0xffffffffu, q40, off);
        s41 += __shfl_xor_sync(0xffffffffu, s41, off);
        q41 += __shfl_xor_sync(0xffffffffu, q41, off);
    }
    if (col == 0) {
        float* P = g_part + (size_t)blockIdx.x*(OUT_*2);
        P[o0*2]        = s20; P[o0*2 + 1]        = q20;
        P[o1*2]        = s21; P[o1*2 + 1]        = q21;
        P[(64+o0)*2]   = s40; P[(64+o0)*2 + 1]   = q40;
        P[(64+o1)*2]   = s41; P[(64+o1)*2 + 1]   = q41;
    }
}

// ============================================================
// Kernel 2: fixed-order reduction of partials -> scale/shift per channel
// ============================================================
__global__ void reduce_k(const float* __restrict__ gamma, const float* __restrict__ beta) {
    int ch = blockIdx.x;
    __shared__ float ss[256], sq[256];
    float s = 0.f, q = 0.f;
    for (int blk = threadIdx.x; blk < NBLK; blk += 256) {
        const float* P = g_part + (size_t)blk*(OUT_*2) + ch*2;
        s += P[0]; q += P[1];
    }
    ss[threadIdx.x] = s; sq[threadIdx.x] = q;
    __syncthreads();
    for (int off = 128; off > 0; off >>= 1) {
        if (threadIdx.x < off) {
            ss[threadIdx.x] += ss[threadIdx.x + off];
            sq[threadIdx.x] += sq[threadIdx.x + off];
        }
        __syncthreads();
    }
    if (threadIdx.x == 0) {
        float mean = ss[0] / (float)G_;
        float var  = sq[0] / (float)G_ - mean*mean;
        float sc   = gamma[ch] * rsqrtf(var + EPS_);
        g_scale[ch] = sc;
        g_shift[ch] = beta[ch] - mean*sc;
    }
}

// ============================================================
// Kernel 3: apply batchnorm in place (float4)
// ============================================================
__global__ void bn_k(float* __restrict__ out) {
    int i  = blockIdx.x*blockDim.x + threadIdx.x;     // over 1,048,576 float4
    int ch = (i >> 9) & 127;                          // 512 float4 per (b,ch) row
    float sc = g_scale[ch], sh = g_shift[ch];
    float4 v = ((float4*)out)[i];
    v.x = v.x*sc + sh; v.y = v.y*sc + sh;
    v.z = v.z*sc + sh; v.w = v.w*sc + sh;
    ((float4*)out)[i] = v;
}

// ============================================================
extern "C" void kernel_launch(void* const* d_in, const int* in_sizes, int n_in,
                              void* d_out, int out_size) {
    const float* x     = (const float*)d_in[0];
    const int*   sidx  = (const int*)  d_in[1];
    const float* adjw  = (const float*)d_in[2];
    const float* W2    = (const float*)d_in[3];
    const float* b2    = (const float*)d_in[4];
    const float* W4    = (const float*)d_in[5];
    const float* gamma = (const float*)d_in[6];
    const float* beta  = (const float*)d_in[7];
    float* out = (float*)d_out;

    dim3 tb(32, 8);
    dim3 tg(N_/32, C_/32, B_);
    transpose_k<<<tg, tb>>>(x);

    pq_k<<<G_/64, 256>>>(W4);

    const int smem = (TN*FSTR*2 + TN*400) * (int)sizeof(float) + TN*K_*(int)sizeof(int); // 95,616 B
    cudaFuncSetAttribute(main_k, cudaFuncAttributeMaxDynamicSharedMemorySize, smem);
    main_k<<<NBLK, THR, smem>>>(sidx, adjw, W2, b2, out);

    reduce_k<<<OUT_, 256>>>(gamma, beta);
    bn_k<<<(G_*OUT_/4)/256, 256>>>(out);
}

// round 10
// speedup vs baseline: 1.1416x; 1.1416x over previous
#include <cuda_runtime.h>
#include <math.h>
#include <float.h>

#define B_   16
#define C_   64
#define N_   2048
#define K_   20
#define OUT_ 128
#define G_   (B_*N_)          // 32768 columns
#define TN   8                // columns per block
#define NBLK (G_/TN)          // 4096
#define THR  256
#define FSTR 1284             // padded per-column stride (floats)
#define EPS_ 1e-5f

// ---- device scratch (no allocations allowed) ----
__device__ float g_xT[G_*C_];             // 8 MB: x transposed to (B*N, C)
__device__ float g_P[G_*64];              // 8 MB: P[p][o] = W4a . xT[p]
__device__ float g_Q[G_*64];              // 8 MB: Q[g][o] = (W4b-W4a) . xT[g]
__device__ float g_part[NBLK*OUT_*2];     // 4 MB: per-block (sum, sumsq) per channel
__device__ float g_scale[OUT_];
__device__ float g_shift[OUT_];

// ============================================================
// Kernel 0: transpose x (B,C,N) -> xT (B*N, C), smem-tiled
// ============================================================
__global__ void transpose_k(const float* __restrict__ x) {
    __shared__ float t[32][33];
    int b  = blockIdx.z;
    int n0 = blockIdx.x * 32, c0 = blockIdx.y * 32;
    int tx = threadIdx.x, ty = threadIdx.y;
    #pragma unroll
    for (int i = ty; i < 32; i += 8)
        t[i][tx] = x[((size_t)b*C_ + c0 + i)*N_ + n0 + tx];
    __syncthreads();
    #pragma unroll
    for (int i = ty; i < 32; i += 8)
        g_xT[((size_t)b*N_ + n0 + i)*C_ + c0 + tx] = t[tx][i];
}

// ============================================================
// Kernel 0b: P/Q precompute.  P[p][o] = sum_c W4a[o][c] xT[p][c],
//            Q[p][o] = sum_c (W4b-W4a)[o][c] xT[p][c].
// ============================================================
__global__ __launch_bounds__(256)
void pq_k(const float* __restrict__ W4) {
    __shared__ float X[64*68];
    __shared__ float WW[128*68];
    const int tid = threadIdx.x;
    const int p0  = blockIdx.x * 64;

    // WW rows 0..63 = W4a, rows 64..127 = W4b - W4a
    for (int j = tid; j < 64*16; j += 256) {
        int o = j >> 4, q = j & 15;
        float4 a = ((const float4*)W4)[o*32 + q];
        float4 b = ((const float4*)W4)[o*32 + 16 + q];
        float* d = &WW[o*68 + q*4];
        d[0]=a.x; d[1]=a.y; d[2]=a.z; d[3]=a.w;
        float* e = &WW[(64+o)*68 + q*4];
        e[0]=b.x-a.x; e[1]=b.y-a.y; e[2]=b.z-a.z; e[3]=b.w-a.w;
    }
    for (int j = tid; j < 64*16; j += 256) {
        int r = j >> 4, q = j & 15;
        float4 v = ((const float4*)g_xT)[(size_t)(p0 + r)*16 + q];
        float* d = &X[r*68 + q*4];
        d[0]=v.x; d[1]=v.y; d[2]=v.z; d[3]=v.w;
    }
    __syncthreads();

    const int o  = tid & 63;
    const int ps = tid >> 6;                 // 0..3 -> 16 p-rows each
    const float4* wa = (const float4*)(WW + o*68);
    const float4* wb = (const float4*)(WW + (64+o)*68);
    for (int pl = 0; pl < 16; pl++) {
        int p = ps*16 + pl;
        const float4* xv = (const float4*)(X + p*68);
        float aA0=0.f, aA1=0.f, aB0=0.f, aB1=0.f;
        #pragma unroll
        for (int q = 0; q < 16; q++) {
            float4 xq = xv[q], u = wa[q], v = wb[q];
            aA0 += xq.x*u.x + xq.y*u.y;  aA1 += xq.z*u.z + xq.w*u.w;
            aB0 += xq.x*v.x + xq.y*v.y;  aB1 += xq.z*v.z + xq.w*v.w;
        }
        g_P[(size_t)(p0 + p)*64 + o] = aA0 + aA1;
        g_Q[(size_t)(p0 + p)*64 + o] = aB0 + aB1;
    }
}

// ============================================================
// Kernel 1: fused gather + feats + out2 + out4 + partial stats
//   R8 skeleton; ONLY change: out2 uses col-pair map (o = tid>>2,
//   2 columns per thread) with unroll 4, results exchanged via AW.
//   out4 keeps R8's direct __ldg gather from g_P.
// ============================================================
__global__ __launch_bounds__(THR, 2)
void main_k(const int*   __restrict__ sidx,
            const float* __restrict__ adjw,
            const float* __restrict__ W2,
            const float* __restrict__ b2,
            float*       __restrict__ out)
{
    extern __shared__ float sm[];
    float* S  = sm;                      // TN*FSTR: S[col][i*64+f]
    float* F  = S + TN*FSTR;             // TN*FSTR: feats[col][f*20+k]
    float* AW = F + TN*FSTR;             // TN*400: A[col][i*20+k]; later o2 scratch [col*64+o]
    int*   SX = (int*)(AW + TN*400);     // TN*20 spiral indices

    const int tid = threadIdx.x;
    const int g0  = blockIdx.x * TN;

    // ---- stage spiral indices ----
    if (tid < TN*K_) SX[tid] = sidx[g0*K_ + tid];      // SX[col*20+i]

    // ---- gather spiral rows into S (float4, coalesced over xT rows) ----
    for (int j = tid; j < TN*K_*16; j += THR) {
        int col = j / (K_*16);
        int r   = j % (K_*16);
        int i   = r >> 4, q = r & 15;
        int p   = sidx[(g0 + col)*K_ + i];
        float4 v = ((const float4*)g_xT)[(size_t)p*16 + q];
        float* d = &S[col*FSTR + i*64 + q*4];
        d[0]=v.x; d[1]=v.y; d[2]=v.z; d[3]=v.w;
    }
    // ---- adjweight tile ----
    for (int j = tid; j < TN*100; j += THR) {
        int col = j/100, q = j%100;
        float4 v = ((const float4*)adjw)[(size_t)(g0+col)*100 + q];
        float* d = &AW[col*400 + q*4];
        d[0]=v.x; d[1]=v.y; d[2]=v.z; d[3]=v.w;
    }
    __syncthreads();

    // ---- feats[col][f*20+k] = sum_i S[col][i][f] * A[col][i][k] ----
    #pragma unroll
    for (int pass = 0; pass < 2; pass++) {
        int id   = tid + pass*THR;
        int fcol = id >> 6, f = id & 63;
        float acc[20];
        #pragma unroll
        for (int k = 0; k < 20; k++) acc[k] = 0.f;
        const float* Sc = S  + fcol*FSTR + f;
        const float* Ac = AW + fcol*400;
        #pragma unroll
        for (int i = 0; i < 20; i++) {
            float sv = Sc[i*64];
            #pragma unroll
            for (int k = 0; k < 20; k++) acc[k] += sv * Ac[i*20 + k];
        }
        float* Fd = F + fcol*FSTR + f*20;
        #pragma unroll
        for (int k = 0; k < 20; k++) Fd[k] = acc[k];
    }
    __syncthreads();   // AW (adjweight) free after this point

    // ---- out2: col-pair map.  o = tid>>2 (0..63), cols {2cp, 2cp+1}.
    //      Each W2 row segment loaded once serves 2 columns. unroll 4
    //      keeps in-flight load regs at ~48 (spill-safe under 128-reg cap).
    {
        const int o  = tid >> 2;
        const int cp = tid & 3;
        const int cA = cp*2, cB = cp*2 + 1;
        const float4* w  = (const float4*)(W2 + (size_t)o*1280);
        const float4* fA = (const float4*)(F + cA*FSTR);
        const float4* fB = (const float4*)(F + cB*FSTR);
        float aAx=0.f,aAy=0.f,aAz=0.f,aAw=0.f;
        float aBx=0.f,aBy=0.f,aBz=0.f,aBw=0.f;
        #pragma unroll 4
        for (int q = 0; q < 320; q++) {
            float4 u  = w[q];
            float4 pa = fA[q], pb = fB[q];
            aAx += pa.x*u.x; aAy += pa.y*u.y; aAz += pa.z*u.z; aAw += pa.w*u.w;
            aBx += pb.x*u.x; aBy += pb.y*u.y; aBz += pb.z*u.z; aBw += pb.w*u.w;
        }
        float bb = b2[o];
        AW[cA*64 + o] = aAx + aAy + aAz + aAw + bb;
        AW[cB*64 + o] = aBx + aBy + aBz + aBw + bb;
    }
    __syncthreads();

    // ---- phase 4: out4 via direct P gather (R8 form), combine, write, stats
    const int o0  = tid >> 3;        // 0..31
    const int o1  = o0 + 32;         // 32..63
    const int col = tid & 7;
    const int g   = g0 + col;

    // hoist Q loads so their latency hides under the P gather
    float q0 = __ldg(&g_Q[(size_t)g*64 + o0]);
    float q1 = __ldg(&g_Q[(size_t)g*64 + o1]);

    float v20 = AW[col*64 + o0];
    float v21 = AW[col*64 + o1];

    float m0 = -FLT_MAX, m1 = -FLT_MAX;
    {
        const int* sxc = SX + col*K_;
        #pragma unroll
        for (int half = 0; half < 2; half++) {
            float pv0[10], pv1[10];
            #pragma unroll
            for (int i = 0; i < 10; i++) {
                size_t p = (size_t)sxc[half*10 + i] * 64;
                pv0[i] = __ldg(&g_P[p + o0]);
                pv1[i] = __ldg(&g_P[p + o1]);
            }
            #pragma unroll
            for (int i = 0; i < 10; i++) {
                m0 = fmaxf(m0, pv0[i]);
                m1 = fmaxf(m1, pv1[i]);
            }
        }
    }
    float v40 = m0 + q0;
    float v41 = m1 + q1;

    // ---- write pre-BN outputs ----
    {
        int b = g >> 11, n = g & 2047;
        size_t base = ((size_t)b*OUT_)*N_ + n;
        out[base + (size_t)o0*N_]        = v20;
        out[base + (size_t)o1*N_]        = v21;
        out[base + (size_t)(64+o0)*N_]   = v40;
        out[base + (size_t)(64+o1)*N_]   = v41;
    }

    // ---- deterministic per-block stats: butterfly over the 3 col bits ----
    float s20=v20, q20=v20*v20, s21=v21, q21=v21*v21;
    float s40=v40, q40=v40*v40, s41=v41, q41=v41*v41;
    #pragma unroll
    for (int off = 1; off < 8; off <<= 1) {
        s20 += __shfl_xor_sync(0xffffffffu, s20, off);
        q20 += __shfl_xor_sync(0xffffffffu, q20, off);
        s21 += __shfl_xor_sync(0xffffffffu, s21, off);
        q21 += __shfl_xor_sync(0xffffffffu, q21, off);
        s40 += __shfl_xor_sync(0xffffffffu, s40, off);
        q40 += __shfl_xor_sync(0xffffffffu, q40, off);
        s41 += __shfl_xor_sync(0xffffffffu, s41, off);
        q41 += __shfl_xor_sync(0xffffffffu, q41, off);
    }
    if (col == 0) {
        float* P = g_part + (size_t)blockIdx.x*(OUT_*2);
        P[o0*2]        = s20; P[o0*2 + 1]        = q20;
        P[o1*2]        = s21; P[o1*2 + 1]        = q21;
        P[(64+o0)*2]   = s40; P[(64+o0)*2 + 1]   = q40;
        P[(64+o1)*2]   = s41; P[(64+o1)*2 + 1]   = q41;
    }
}

// ============================================================
// Kernel 2: fixed-order reduction of partials -> scale/shift per channel
// ============================================================
__global__ void reduce_k(const float* __restrict__ gamma, const float* __restrict__ beta) {
    int ch = blockIdx.x;
    __shared__ float ss[256], sq[256];
    float s = 0.f, q = 0.f;
    for (int blk = threadIdx.x; blk < NBLK; blk += 256) {
        const float* P = g_part + (size_t)blk*(OUT_*2) + ch*2;
        s += P[0]; q += P[1];
    }
    ss[threadIdx.x] = s; sq[threadIdx.x] = q;
    __syncthreads();
    for (int off = 128; off > 0; off >>= 1) {
        if (threadIdx.x < off) {
            ss[threadIdx.x] += ss[threadIdx.x + off];
            sq[threadIdx.x] += sq[threadIdx.x + off];
        }
        __syncthreads();
    }
    if (threadIdx.x == 0) {
        float mean = ss[0] / (float)G_;
        float var  = sq[0] / (float)G_ - mean*mean;
        float sc   = gamma[ch] * rsqrtf(var + EPS_);
        g_scale[ch] = sc;
        g_shift[ch] = beta[ch] - mean*sc;
    }
}

// ============================================================
// Kernel 3: apply batchnorm in place (float4)
// ============================================================
__global__ void bn_k(float* __restrict__ out) {
    int i  = blockIdx.x*blockDim.x + threadIdx.x;     // over 1,048,576 float4
    int ch = (i >> 9) & 127;                          // 512 float4 per (b,ch) row
    float sc = g_scale[ch], sh = g_shift[ch];
    float4 v = ((float4*)out)[i];
    v.x = v.x*sc + sh; v.y = v.y*sc + sh;
    v.z = v.z*sc + sh; v.w = v.w*sc + sh;
    ((float4*)out)[i] = v;
}

// ============================================================
extern "C" void kernel_launch(void* const* d_in, const int* in_sizes, int n_in,
                              void* d_out, int out_size) {
    const float* x     = (const float*)d_in[0];
    const int*   sidx  = (const int*)  d_in[1];
    const float* adjw  = (const float*)d_in[2];
    const float* W2    = (const float*)d_in[3];
    const float* b2    = (const float*)d_in[4];
    const float* W4    = (const float*)d_in[5];
    const float* gamma = (const float*)d_in[6];
    const float* beta  = (const float*)d_in[7];
    float* out = (float*)d_out;

    dim3 tb(32, 8);
    dim3 tg(N_/32, C_/32, B_);
    transpose_k<<<tg, tb>>>(x);

    pq_k<<<G_/64, 256>>>(W4);

    const int smem = (TN*FSTR*2 + TN*400) * (int)sizeof(float) + TN*K_*(int)sizeof(int); // 95,616 B
    cudaFuncSetAttribute(main_k, cudaFuncAttributeMaxDynamicSharedMemorySize, smem);
    main_k<<<NBLK, THR, smem>>>(sidx, adjw, W2, b2, out);

    reduce_k<<<OUT_, 256>>>(gamma, beta);
    bn_k<<<(G_*OUT_/4)/256, 256>>>(out);
}

// round 11
// speedup vs baseline: 1.4521x; 1.2719x over previous
#include <cuda_runtime.h>
#include <math.h>
#include <float.h>

#define B_   16
#define C_   64
#define N_   2048
#define K_   20
#define OUT_ 128
#define G_   (B_*N_)          // 32768 columns
#define TN   8                // columns per block
#define NBLK (G_/TN)          // 4096
#define THR  256
#define FSTR 1284             // padded per-column stride (floats)
#define WCH  128              // W2 columns per staged chunk
#define WSTR 132              // staged W2 row stride (banks spread: 132 mod 32 = 4)
#define NCH  (1280/WCH)       // 10 chunks
#define EPS_ 1e-5f

// ---- device scratch (no allocations allowed) ----
__device__ float g_xT[G_*C_];             // 8 MB: x transposed to (B*N, C)
__device__ float g_P[G_*64];              // 8 MB: P[p][o] = W4a . xT[p]
__device__ float g_Q[G_*64];              // 8 MB: Q[g][o] = (W4b-W4a) . xT[g]
__device__ float g_part[NBLK*OUT_*2];     // 4 MB: per-block (sum, sumsq) per channel
__device__ float g_scale[OUT_];
__device__ float g_shift[OUT_];

// ============================================================
// Kernel 0: transpose x (B,C,N) -> xT (B*N, C), smem-tiled
// ============================================================
__global__ void transpose_k(const float* __restrict__ x) {
    __shared__ float t[32][33];
    int b  = blockIdx.z;
    int n0 = blockIdx.x * 32, c0 = blockIdx.y * 32;
    int tx = threadIdx.x, ty = threadIdx.y;
    #pragma unroll
    for (int i = ty; i < 32; i += 8)
        t[i][tx] = x[((size_t)b*C_ + c0 + i)*N_ + n0 + tx];
    __syncthreads();
    #pragma unroll
    for (int i = ty; i < 32; i += 8)
        g_xT[((size_t)b*N_ + n0 + i)*C_ + c0 + tx] = t[tx][i];
}

// ============================================================
// Kernel 0b: P/Q precompute.  P[p][o] = sum_c W4a[o][c] xT[p][c],
//            Q[p][o] = sum_c (W4b-W4a)[o][c] xT[p][c].
// ============================================================
__global__ __launch_bounds__(256)
void pq_k(const float* __restrict__ W4) {
    __shared__ float X[64*68];
    __shared__ float WW[128*68];
    const int tid = threadIdx.x;
    const int p0  = blockIdx.x * 64;

    // WW rows 0..63 = W4a, rows 64..127 = W4b - W4a
    for (int j = tid; j < 64*16; j += 256) {
        int o = j >> 4, q = j & 15;
        float4 a = ((const float4*)W4)[o*32 + q];
        float4 b = ((const float4*)W4)[o*32 + 16 + q];
        float* d = &WW[o*68 + q*4];
        d[0]=a.x; d[1]=a.y; d[2]=a.z; d[3]=a.w;
        float* e = &WW[(64+o)*68 + q*4];
        e[0]=b.x-a.x; e[1]=b.y-a.y; e[2]=b.z-a.z; e[3]=b.w-a.w;
    }
    for (int j = tid; j < 64*16; j += 256) {
        int r = j >> 4, q = j & 15;
        float4 v = ((const float4*)g_xT)[(size_t)(p0 + r)*16 + q];
        float* d = &X[r*68 + q*4];
        d[0]=v.x; d[1]=v.y; d[2]=v.z; d[3]=v.w;
    }
    __syncthreads();

    const int o  = tid & 63;
    const int ps = tid >> 6;                 // 0..3 -> 16 p-rows each
    const float4* wa = (const float4*)(WW + o*68);
    const float4* wb = (const float4*)(WW + (64+o)*68);
    for (int pl = 0; pl < 16; pl++) {
        int p = ps*16 + pl;
        const float4* xv = (const float4*)(X + p*68);
        float aA0=0.f, aA1=0.f, aB0=0.f, aB1=0.f;
        #pragma unroll
        for (int q = 0; q < 16; q++) {
            float4 xq = xv[q], u = wa[q], v = wb[q];
            aA0 += xq.x*u.x + xq.y*u.y;  aA1 += xq.z*u.z + xq.w*u.w;
            aB0 += xq.x*v.x + xq.y*v.y;  aB1 += xq.z*v.z + xq.w*v.w;
        }
        g_P[(size_t)(p0 + p)*64 + o] = aA0 + aA1;
        g_Q[(size_t)(p0 + p)*64 + o] = aB0 + aB1;
    }
}

// ============================================================
// Kernel 1: fused gather + feats + out2 + out4 + partial stats
//   R8 skeleton; ONLY change: out2 streams W2 through smem chunks
//   (staged into the retired S region) instead of per-thread LDG.
// ============================================================
__global__ __launch_bounds__(THR, 2)
void main_k(const int*   __restrict__ sidx,
            const float* __restrict__ adjw,
            const float* __restrict__ W2,
            const float* __restrict__ b2,
            float*       __restrict__ out)
{
    extern __shared__ float sm[];
    float* S  = sm;                      // TN*FSTR: S[col][i*64+f]; later W2 chunk [64][WSTR]
    float* F  = S + TN*FSTR;             // TN*FSTR: feats[col][f*20+k]
    float* AW = F + TN*FSTR;             // TN*400: A[col][i*20+k]
    int*   SX = (int*)(AW + TN*400);     // TN*20 spiral indices

    const int tid = threadIdx.x;
    const int g0  = blockIdx.x * TN;

    // ---- stage spiral indices ----
    if (tid < TN*K_) SX[tid] = sidx[g0*K_ + tid];      // SX[col*20+i]

    // ---- gather spiral rows into S (float4, coalesced over xT rows) ----
    for (int j = tid; j < TN*K_*16; j += THR) {
        int col = j / (K_*16);
        int r   = j % (K_*16);
        int i   = r >> 4, q = r & 15;
        int p   = sidx[(g0 + col)*K_ + i];
        float4 v = ((const float4*)g_xT)[(size_t)p*16 + q];
        float* d = &S[col*FSTR + i*64 + q*4];
        d[0]=v.x; d[1]=v.y; d[2]=v.z; d[3]=v.w;
    }
    // ---- adjweight tile ----
    for (int j = tid; j < TN*100; j += THR) {
        int col = j/100, q = j%100;
        float4 v = ((const float4*)adjw)[(size_t)(g0+col)*100 + q];
        float* d = &AW[col*400 + q*4];
        d[0]=v.x; d[1]=v.y; d[2]=v.z; d[3]=v.w;
    }
    __syncthreads();

    // ---- feats[col][f*20+k] = sum_i S[col][i][f] * A[col][i][k] ----
    #pragma unroll
    for (int pass = 0; pass < 2; pass++) {
        int id   = tid + pass*THR;
        int fcol = id >> 6, f = id & 63;
        float acc[20];
        #pragma unroll
        for (int k = 0; k < 20; k++) acc[k] = 0.f;
        const float* Sc = S  + fcol*FSTR + f;
        const float* Ac = AW + fcol*400;
        #pragma unroll
        for (int i = 0; i < 20; i++) {
            float sv = Sc[i*64];
            #pragma unroll
            for (int k = 0; k < 20; k++) acc[k] += sv * Ac[i*20 + k];
        }
        float* Fd = F + fcol*FSTR + f*20;
        #pragma unroll
        for (int k = 0; k < 20; k++) Fd[k] = acc[k];
    }

    const int o0  = tid >> 3;        // 0..31
    const int o1  = o0 + 32;         // 32..63
    const int col = tid & 7;
    const int g   = g0 + col;

    // ---- out2: W2 @ feats, W2 staged through smem in NCH chunks.
    //      Thread map identical to R8; w reads are 8-lane broadcasts of
    //      4 distinct rows per warp, rows spread over banks by WSTR=132.
    float a0x=0.f,a0y=0.f,a0z=0.f,a0w=0.f;
    float a1x=0.f,a1y=0.f,a1z=0.f,a1w=0.f;
    for (int ch = 0; ch < NCH; ch++) {
        __syncthreads();   // S free (first iter: feats done reading S; later: prev chunk consumed)
        for (int j = tid; j < 64*(WCH/4); j += THR) {
            int row = j >> 5, q = j & 31;
            float4 v = ((const float4*)(W2 + (size_t)row*1280 + ch*WCH))[q];
            float* d = &S[row*WSTR + q*4];
            d[0]=v.x; d[1]=v.y; d[2]=v.z; d[3]=v.w;
        }
        __syncthreads();
        const float4* w0 = (const float4*)(S + o0*WSTR);
        const float4* w1 = (const float4*)(S + o1*WSTR);
        const float4* fv = (const float4*)(F + col*FSTR) + ch*(WCH/4);
        #pragma unroll 8
        for (int q = 0; q < WCH/4; q++) {
            float4 fq = fv[q];
            float4 u  = w0[q], v = w1[q];
            a0x += fq.x*u.x; a0y += fq.y*u.y; a0z += fq.z*u.z; a0w += fq.w*u.w;
            a1x += fq.x*v.x; a1y += fq.y*v.y; a1z += fq.z*v.z; a1w += fq.w*v.w;
        }
    }
    float v20 = a0x + a0y + a0z + a0w + b2[o0];
    float v21 = a1x + a1y + a1z + a1w + b2[o1];

    // ---- out4: max over 20 gathered P values (chunks of 10 for MLP) + Q ----
    float q0 = __ldg(&g_Q[(size_t)g*64 + o0]);
    float q1 = __ldg(&g_Q[(size_t)g*64 + o1]);
    float m0 = -FLT_MAX, m1 = -FLT_MAX;
    {
        const int* sxc = SX + col*K_;
        #pragma unroll
        for (int half = 0; half < 2; half++) {
            float pv0[10], pv1[10];
            #pragma unroll
            for (int i = 0; i < 10; i++) {
                size_t p = (size_t)sxc[half*10 + i] * 64;
                pv0[i] = __ldg(&g_P[p + o0]);
                pv1[i] = __ldg(&g_P[p + o1]);
            }
            #pragma unroll
            for (int i = 0; i < 10; i++) {
                m0 = fmaxf(m0, pv0[i]);
                m1 = fmaxf(m1, pv1[i]);
            }
        }
    }
    float v40 = m0 + q0;
    float v41 = m1 + q1;

    // ---- write pre-BN outputs ----
    {
        int b = g >> 11, n = g & 2047;
        size_t base = ((size_t)b*OUT_)*N_ + n;
        out[base + (size_t)o0*N_]        = v20;
        out[base + (size_t)o1*N_]        = v21;
        out[base + (size_t)(64+o0)*N_]   = v40;
        out[base + (size_t)(64+o1)*N_]   = v41;
    }

    // ---- deterministic per-block stats: butterfly over the 3 col bits ----
    float s20=v20, q20=v20*v20, s21=v21, q21=v21*v21;
    float s40=v40, q40=v40*v40, s41=v41, q41=v41*v41;
    #pragma unroll
    for (int off = 1; off < 8; off <<= 1) {
        s20 += __shfl_xor_sync(0xffffffffu, s20, off);
        q20 += __shfl_xor_sync(0xffffffffu, q20, off);
        s21 += __shfl_xor_sync(0xffffffffu, s21, off);
        q21 += __shfl_xor_sync(0xffffffffu, q21, off);
        s40 += __shfl_xor_sync(0xffffffffu, s40, off);
        q40 += __shfl_xor_sync(0xffffffffu, q40, off);
        s41 += __shfl_xor_sync(0xffffffffu, s41, off);
        q41 += __shfl_xor_sync(0xffffffffu, q41, off);
    }
    if (col == 0) {
        float* P = g_part + (size_t)blockIdx.x*(OUT_*2);
        P[o0*2]        = s20; P[o0*2 + 1]        = q20;
        P[o1*2]        = s21; P[o1*2 + 1]        = q21;
        P[(64+o0)*2]   = s40; P[(64+o0)*2 + 1]   = q40;
        P[(64+o1)*2]   = s41; P[(64+o1)*2 + 1]   = q41;
    }
}

// ============================================================
// Kernel 2: fixed-order reduction of partials -> scale/shift per channel
// ============================================================
__global__ void reduce_k(const float* __restrict__ gamma, const float* __restrict__ beta) {
    int ch = blockIdx.x;
    __shared__ float ss[256], sq[256];
    float s = 0.f, q = 0.f;
    for (int blk = threadIdx.x; blk < NBLK; blk += 256) {
        const float* P = g_part + (size_t)blk*(OUT_*2) + ch*2;
        s += P[0]; q += P[1];
    }
    ss[threadIdx.x] = s; sq[threadIdx.x] = q;
    __syncthreads();
    for (int off = 128; off > 0; off >>= 1) {
        if (threadIdx.x < off) {
            ss[threadIdx.x] += ss[threadIdx.x + off];
            sq[threadIdx.x] += sq[threadIdx.x + off];
        }
        __syncthreads();
    }
    if (threadIdx.x == 0) {
        float mean = ss[0] / (float)G_;
        float var  = sq[0] / (float)G_ - mean*mean;
        float sc   = gamma[ch] * rsqrtf(var + EPS_);
        g_scale[ch] = sc;
        g_shift[ch] = beta[ch] - mean*sc;
    }
}

// ============================================================
// Kernel 3: apply batchnorm in place (float4)
// ============================================================
__global__ void bn_k(float* __restrict__ out) {
    int i  = blockIdx.x*blockDim.x + threadIdx.x;     // over 1,048,576 float4
    int ch = (i >> 9) & 127;                          // 512 float4 per (b,ch) row
    float sc = g_scale[ch], sh = g_shift[ch];
    float4 v = ((float4*)out)[i];
    v.x = v.x*sc + sh; v.y = v.y*sc + sh;
    v.z = v.z*sc + sh; v.w = v.w*sc + sh;
    ((float4*)out)[i] = v;
}

// ============================================================
extern "C" void kernel_launch(void* const* d_in, const int* in_sizes, int n_in,
                              void* d_out, int out_size) {
    const float* x     = (const float*)d_in[0];
    const int*   sidx  = (const int*)  d_in[1];
    const float* adjw  = (const float*)d_in[2];
    const float* W2    = (const float*)d_in[3];
    const float* b2    = (const float*)d_in[4];
    const float* W4    = (const float*)d_in[5];
    const float* gamma = (const float*)d_in[6];
    const float* beta  = (const float*)d_in[7];
    float* out = (float*)d_out;

    dim3 tb(32, 8);
    dim3 tg(N_/32, C_/32, B_);
    transpose_k<<<tg, tb>>>(x);

    pq_k<<<G_/64, 256>>>(W4);

    const int smem = (TN*FSTR*2 + TN*400) * (int)sizeof(float) + TN*K_*(int)sizeof(int); // 95,616 B
    cudaFuncSetAttribute(main_k, cudaFuncAttributeMaxDynamicSharedMemorySize, smem);
    main_k<<<NBLK, THR, smem>>>(sidx, adjw, W2, b2, out);

    reduce_k<<<OUT_, 256>>>(gamma, beta);
    bn_k<<<(G_*OUT_/4)/256, 256>>>(out);
}